// round 8
// baseline (speedup 1.0000x reference)
#include <cuda_runtime.h>
#include <cuda_bf16.h>

#define N_ENTS  50000
#define N_EDGES 500000
#define RANK    128
#define SLOPE   0.22916666666666666f   // (1/8 + 1/3)/2

typedef unsigned int u32;

// ---------------- device scratch (allocation-free rule) ----------------
__device__ int   g_deg[N_ENTS];
__device__ int   g_rowptr[N_ENTS + 1];
__device__ int   g_cursor[N_ENTS];
__device__ int   g_colsrc[N_EDGES];
__device__ int   g_colet[N_EDGES];
__device__ float g_h1[(size_t)N_ENTS * RANK];
__device__ float g_sumrel[(size_t)N_ENTS * RANK];
// A' bf16 [N_ENTS][256]: cols 0-127 = scaled agg, cols 128-255 = h
__device__ __nv_bfloat16 g_Ahi[(size_t)N_ENTS * 256];
__device__ __nv_bfloat16 g_Alo[(size_t)N_ENTS * 256];
// W' bf16 [layer][region hi/lo][n=128][k=256] (k contiguous; k<128: Wn, else Wl)
__device__ __nv_bfloat16 g_Wt[2 * 2 * 128 * 256];
__device__ int   g_deg0_list[N_ENTS];
__device__ int   g_deg0_count;

// ---------------- helpers ----------------
__device__ __forceinline__ u32 smem_u32(const void* p) {
    u32 a;
    asm("{ .reg .u64 t; cvta.to.shared.u64 t, %1; cvt.u32.u64 %0, t; }"
        : "=r"(a) : "l"(p));
    return a;
}
__device__ __forceinline__ void cpa16(u32 saddr, const void* g) {
    asm volatile("cp.async.ca.shared.global [%0], [%1], 16;"
                 :: "r"(saddr), "l"(g) : "memory");
}
__device__ __forceinline__ void cpa_commit() {
    asm volatile("cp.async.commit_group;" ::: "memory");
}
__device__ __forceinline__ void cpa_wait7() {
    asm volatile("cp.async.wait_group 7;" ::: "memory");
}
__device__ __forceinline__ void ldmx4(u32* r, u32 addr) {
    asm volatile("ldmatrix.sync.aligned.m8n8.x4.shared.b16 {%0,%1,%2,%3}, [%4];"
                 : "=r"(r[0]), "=r"(r[1]), "=r"(r[2]), "=r"(r[3]) : "r"(addr));
}
__device__ __forceinline__ void mma16816(float* c, const u32* a, const u32* b) {
    asm volatile(
        "mma.sync.aligned.m16n8k16.row.col.f32.bf16.bf16.f32 "
        "{%0,%1,%2,%3}, {%4,%5,%6,%7}, {%8,%9}, {%0,%1,%2,%3};"
        : "+f"(c[0]), "+f"(c[1]), "+f"(c[2]), "+f"(c[3])
        : "r"(a[0]), "r"(a[1]), "r"(a[2]), "r"(a[3]), "r"(b[0]), "r"(b[1]));
}
__device__ __forceinline__ void pack4(const float* v, uint2& uh, uint2& ul) {
    unsigned short hb[4], lb[4];
#pragma unroll
    for (int i = 0; i < 4; i++) {
        __nv_bfloat16 h = __float2bfloat16_rn(v[i]);
        __nv_bfloat16 l = __float2bfloat16_rn(v[i] - __bfloat162float(h));
        hb[i] = __bfloat16_as_ushort(h);
        lb[i] = __bfloat16_as_ushort(l);
    }
    uh.x = (u32)hb[0] | ((u32)hb[1] << 16);
    uh.y = (u32)hb[2] | ((u32)hb[3] << 16);
    ul.x = (u32)lb[0] | ((u32)lb[1] << 16);
    ul.y = (u32)lb[2] | ((u32)lb[3] << 16);
}

// ---------------- CSR build ----------------
__global__ void init_kernel() {
    int i = blockIdx.x * blockDim.x + threadIdx.x;
    if (i < N_ENTS) g_deg[i] = 0;
    if (i == 0) g_deg0_count = 0;
}

__global__ void hist_kernel(const int* __restrict__ dst) {
    int e = blockIdx.x * blockDim.x + threadIdx.x;
    if (e < N_EDGES) atomicAdd(&g_deg[dst[e]], 1);
}

__global__ void scan_kernel() {
    __shared__ int sums[1024];
    const int CH = 49;
    int t = threadIdx.x;
    int start = t * CH;
    int end = start + CH; if (end > N_ENTS) end = N_ENTS;
    int s = 0;
    for (int i = start; i < end; i++) s += g_deg[i];
    sums[t] = s;
    __syncthreads();
    for (int off = 1; off < 1024; off <<= 1) {
        int v = (t >= off) ? sums[t - off] : 0;
        __syncthreads();
        sums[t] += v;
        __syncthreads();
    }
    int run = sums[t] - s;
    for (int i = start; i < end; i++) {
        g_rowptr[i] = run;
        g_cursor[i] = run;
        int d = g_deg[i];
        if (d == 0) {
            int p = atomicAdd(&g_deg0_count, 1);
            g_deg0_list[p] = i;
        }
        run += d;
    }
    if (t == 1023) g_rowptr[N_ENTS] = sums[1023];
}

__global__ void fill_kernel(const int* __restrict__ src, const int* __restrict__ dst,
                            const int* __restrict__ et) {
    int e = blockIdx.x * blockDim.x + threadIdx.x;
    if (e < N_EDGES) {
        int d = dst[e];
        int p = atomicAdd(&g_cursor[d], 1);
        g_colsrc[p] = src[e];
        g_colet[p]  = et[e];
    }
}

// ---------------- prep: weight conversion + ent conversion (merged) -------
#define WTB  ((2 * 2 * 128 * 256 + 255) / 256)
#define ENTB ((N_ENTS * 32 + 255) / 256)
__global__ void prep_kernel(const float* __restrict__ Wn, const float* __restrict__ Wl,
                            const float* __restrict__ ent) {
    if (blockIdx.x < WTB) {
        int idx = blockIdx.x * blockDim.x + threadIdx.x;
        if (idx >= 2 * 2 * 128 * 256) return;
        int k = idx & 255;
        int n = (idx >> 8) & 127;
        int reg = (idx >> 15) & 1;
        int l = idx >> 16;
        const float* W = (k < 128) ? (Wn + l * 16384 + k * 128 + n)
                                   : (Wl + l * 16384 + (k - 128) * 128 + n);
        float v = *W;
        __nv_bfloat16 hi = __float2bfloat16_rn(v);
        __nv_bfloat16 o = reg ? __float2bfloat16_rn(v - __bfloat162float(hi)) : hi;
        g_Wt[idx] = o;
    } else {
        int idx = (blockIdx.x - WTB) * blockDim.x + threadIdx.x;
        if (idx >= N_ENTS * 32) return;
        int row = idx >> 5, q = idx & 31;
        float4 v = reinterpret_cast<const float4*>(ent + (size_t)row * RANK)[q];
        float f[4] = {v.x, v.y, v.z, v.w};
        uint2 uh, ul;
        pack4(f, uh, ul);
        *reinterpret_cast<uint2*>(g_Ahi + (size_t)row * 256 + 128 + q * 4) = uh;
        *reinterpret_cast<uint2*>(g_Alo + (size_t)row * 256 + 128 + q * 4) = ul;
    }
}

// ---------------- aggregation: cp.async pipelined gather ----------------
// warp-per-node, depth-8 SMEM ring; no register-resident in-flight rows.
// mode 0: gather h+rel, store sumrel, write bf16 agg (cols 0-127)
// mode 1: gather h only, add stored sumrel
#define AD 8
__global__ void __launch_bounds__(128)
agg_kernel(const float* __restrict__ h_ext,
           const float* __restrict__ rel,
           const float* __restrict__ norm, int mode) {
    __shared__ float4 hring[4][AD][32];   // 16 KB
    __shared__ float4 rring[4][AD][32];   // 16 KB
    const float* __restrict__ h = h_ext ? h_ext : (const float*)g_h1;

    const int warp = threadIdx.x >> 5;
    const int lane = threadIdx.x & 31;
    const int w = blockIdx.x * 4 + warp;
    if (w >= N_ENTS) return;
    const int e0 = g_rowptr[w], e1 = g_rowptr[w + 1];

    const u32 hbase = smem_u32(&hring[warp][0][lane]);
    const u32 rbase = smem_u32(&rring[warp][0][lane]);

    // prologue: fill pipeline (always commit AD groups, empty beyond e1)
#pragma unroll
    for (int k = 0; k < AD; k++) {
        int e = e0 + k;
        if (e < e1) {
            int s = g_colsrc[e];
            cpa16(hbase + k * 512, h + (size_t)s * RANK + lane * 4);
            if (mode == 0) {
                int t = g_colet[e];
                cpa16(rbase + k * 512, rel + (size_t)t * RANK + lane * 4);
            }
        }
        cpa_commit();
    }

    float4 acc = make_float4(0.f, 0.f, 0.f, 0.f);
    float4 racc = make_float4(0.f, 0.f, 0.f, 0.f);
    int slot = 0;
    for (int j = e0; j < e1; j++) {
        cpa_wait7();                       // oldest of 8 pending groups done
        float4 v = hring[warp][slot][lane];
        acc.x += v.x; acc.y += v.y; acc.z += v.z; acc.w += v.w;
        if (mode == 0) {
            float4 r = rring[warp][slot][lane];
            racc.x += r.x; racc.y += r.y; racc.z += r.z; racc.w += r.w;
        }
        int e = j + AD;                    // refill same slot
        if (e < e1) {
            int s = g_colsrc[e];
            cpa16(hbase + slot * 512, h + (size_t)s * RANK + lane * 4);
            if (mode == 0) {
                int t = g_colet[e];
                cpa16(rbase + slot * 512, rel + (size_t)t * RANK + lane * 4);
            }
        }
        cpa_commit();                      // keep pending count at AD
        slot = (slot + 1) & (AD - 1);
    }

    if (mode == 0) {
        reinterpret_cast<float4*>(g_sumrel + (size_t)w * RANK)[lane] = racc;
    } else {
        racc = reinterpret_cast<const float4*>(g_sumrel + (size_t)w * RANK)[lane];
    }
    float nm = norm[w];
    float f[4] = {(acc.x + racc.x) * nm, (acc.y + racc.y) * nm,
                  (acc.z + racc.z) * nm, (acc.w + racc.w) * nm};
    uint2 uh, ul;
    pack4(f, uh, ul);
    *reinterpret_cast<uint2*>(g_Ahi + (size_t)w * 256 + lane * 4) = uh;
    *reinterpret_cast<uint2*>(g_Alo + (size_t)w * 256 + lane * 4) = ul;
}

// ---------------- bf16-split mma.sync GEMM (R5-proven) ----------------
__global__ void __launch_bounds__(256, 2)
gemm_kernel(int layer, float* __restrict__ out_ext, int write_bf16) {
    float* __restrict__ outf = out_ext ? out_ext : (float*)g_h1;

    __shared__ __align__(16) char sA[128 * 144];
    __shared__ __align__(16) char sB[128 * 144];

    const int tid = threadIdx.x;
    const int lane = tid & 31;
    const int wid = tid >> 5;
    const int warp_m = wid & 3;
    const int warp_n = wid >> 2;
    const int block_row = blockIdx.x * 128;

    const u32 sAu = smem_u32(sA);
    const u32 sBu = smem_u32(sB);

    const int a_q = lane >> 3;
    const int a_row = (lane & 7) + (a_q & 1) * 8;
    const int a_kb = (a_q >> 1) * 16;
    const int b_q = lane >> 3;
    const int b_row = ((b_q >> 1) * 8) + (lane & 7);
    const int b_kb = (b_q & 1) * 16;

    float c[2][8][4];
#pragma unroll
    for (int t = 0; t < 2; t++)
#pragma unroll
        for (int n = 0; n < 8; n++)
#pragma unroll
            for (int r = 0; r < 4; r++) c[t][n][r] = 0.f;

    for (int kc = 0; kc < 12; kc++) {
        const int pass = kc >> 2;
        const __nv_bfloat16* __restrict__ Asrc = (pass < 2) ? g_Ahi : g_Alo;
        const int region = (pass == 1) ? 1 : 0;
        const __nv_bfloat16* __restrict__ Bsrc =
            g_Wt + ((size_t)(layer * 2 + region) << 15);
        const int kcol = (kc & 3) * 64;

        __syncthreads();
#pragma unroll
        for (int i = 0; i < 4; i++) {
            int idx = tid + i * 256;
            int row = idx >> 3;
            int grp = (idx & 7) * 16;
            uint4 va = make_uint4(0u, 0u, 0u, 0u);
            int grow = block_row + row;
            if (grow < N_ENTS)
                va = *reinterpret_cast<const uint4*>(
                    reinterpret_cast<const char*>(Asrc + (size_t)grow * 256 + kcol) + grp);
            *reinterpret_cast<uint4*>(sA + row * 144 + grp) = va;
            uint4 vb = *reinterpret_cast<const uint4*>(
                reinterpret_cast<const char*>(Bsrc + (size_t)row * 256 + kcol) + grp);
            *reinterpret_cast<uint4*>(sB + row * 144 + grp) = vb;
        }
        __syncthreads();

#pragma unroll
        for (int j = 0; j < 4; j++) {
            u32 aa[2][4];
#pragma unroll
            for (int t = 0; t < 2; t++) {
                u32 addr = sAu + (warp_m * 32 + t * 16 + a_row) * 144 + j * 32 + a_kb;
                ldmx4(aa[t], addr);
            }
#pragma unroll
            for (int p = 0; p < 4; p++) {
                u32 bb[4];
                u32 addr = sBu + (warp_n * 64 + p * 16 + b_row) * 144 + j * 32 + b_kb;
                ldmx4(bb, addr);
#pragma unroll
                for (int t = 0; t < 2; t++) {
                    mma16816(c[t][2 * p],     aa[t], bb);
                    mma16816(c[t][2 * p + 1], aa[t], bb + 2);
                }
            }
        }
    }

    const int er = lane >> 2;
    const int ec = (lane & 3) * 2;
#pragma unroll
    for (int t = 0; t < 2; t++) {
#pragma unroll
        for (int half = 0; half < 2; half++) {
            int grow = block_row + warp_m * 32 + t * 16 + er + half * 8;
            if (grow >= N_ENTS) continue;
#pragma unroll
            for (int n = 0; n < 8; n++) {
                int col = warp_n * 64 + n * 8 + ec;
                float v0 = c[t][n][half * 2 + 0];
                float v1 = c[t][n][half * 2 + 1];
                v0 = (v0 >= 0.f) ? v0 : v0 * SLOPE;
                v1 = (v1 >= 0.f) ? v1 : v1 * SLOPE;
                *reinterpret_cast<float2*>(outf + (size_t)grow * RANK + col) =
                    make_float2(v0, v1);
                if (write_bf16) {
                    __nv_bfloat16 h0 = __float2bfloat16_rn(v0);
                    __nv_bfloat16 h1 = __float2bfloat16_rn(v1);
                    __nv_bfloat16 l0 = __float2bfloat16_rn(v0 - __bfloat162float(h0));
                    __nv_bfloat16 l1 = __float2bfloat16_rn(v1 - __bfloat162float(h1));
                    u32 ph = (u32)__bfloat16_as_ushort(h0) |
                             ((u32)__bfloat16_as_ushort(h1) << 16);
                    u32 pl = (u32)__bfloat16_as_ushort(l0) |
                             ((u32)__bfloat16_as_ushort(l1) << 16);
                    *reinterpret_cast<u32*>(g_Ahi + (size_t)grow * 256 + 128 + col) = ph;
                    *reinterpret_cast<u32*>(g_Alo + (size_t)grow * 256 + 128 + col) = pl;
                }
            }
        }
    }
}

// ---------------- deg-0 fixup ----------------
__global__ void fixup_kernel(const float* __restrict__ h_ext,
                             const float* __restrict__ Wa,
                             float* __restrict__ out_ext, int write_bf16) {
    const float* __restrict__ h = h_ext ? h_ext : (const float*)g_h1;
    float* __restrict__ Out = out_ext ? out_ext : (float*)g_h1;
    int wg = (blockIdx.x * blockDim.x + threadIdx.x) >> 5;
    int lane = threadIdx.x & 31;
    int nwarp = (gridDim.x * blockDim.x) >> 5;
    int cnt = g_deg0_count;
    for (int idx = wg; idx < cnt; idx += nwarp) {
        int v = g_deg0_list[idx];
        const float* hr = h + (size_t)v * RANK;
        float4 acc = make_float4(0.f, 0.f, 0.f, 0.f);
        for (int k = 0; k < RANK; k++) {
            float a = hr[k];
            float4 wv = reinterpret_cast<const float4*>(Wa + (size_t)k * RANK)[lane];
            acc.x += a * wv.x; acc.y += a * wv.y;
            acc.z += a * wv.z; acc.w += a * wv.w;
        }
        float f[4];
        f[0] = (acc.x >= 0.f) ? acc.x : acc.x * SLOPE;
        f[1] = (acc.y >= 0.f) ? acc.y : acc.y * SLOPE;
        f[2] = (acc.z >= 0.f) ? acc.z : acc.z * SLOPE;
        f[3] = (acc.w >= 0.f) ? acc.w : acc.w * SLOPE;
        reinterpret_cast<float4*>(Out + (size_t)v * RANK)[lane] =
            make_float4(f[0], f[1], f[2], f[3]);
        if (write_bf16) {
            uint2 uh, ul;
            pack4(f, uh, ul);
            *reinterpret_cast<uint2*>(g_Ahi + (size_t)v * 256 + 128 + lane * 4) = uh;
            *reinterpret_cast<uint2*>(g_Alo + (size_t)v * 256 + 128 + lane * 4) = ul;
        }
    }
}

// ---------------- launch ----------------
extern "C" void kernel_launch(void* const* d_in, const int* in_sizes, int n_in,
                              void* d_out, int out_size) {
    const float* ent  = (const float*)d_in[0];
    const float* rel  = (const float*)d_in[1];
    const float* norm = (const float*)d_in[2];
    const float* Wn   = (const float*)d_in[3];
    const float* Wl   = (const float*)d_in[4];
    const float* Wa   = (const float*)d_in[5];
    const int*   src  = (const int*)d_in[6];
    const int*   dst  = (const int*)d_in[7];
    const int*   et   = (const int*)d_in[8];
    float* out = (float*)d_out;

    const int NB  = (N_ENTS + 255) / 256;
    const int EB  = (N_EDGES + 255) / 256;
    const int AGB = (N_ENTS + 3) / 4;      // 4 node-warps per 128-thr block
    const int GB  = (N_ENTS + 127) / 128;

    init_kernel<<<NB, 256>>>();
    hist_kernel<<<EB, 256>>>(dst);
    scan_kernel<<<1, 1024>>>();
    fill_kernel<<<EB, 256>>>(src, dst, et);
    prep_kernel<<<WTB + ENTB, 256>>>(Wn, Wl, ent);

    const int WSTRIDE = RANK * RANK;

    // layer 0
    agg_kernel<<<AGB, 128>>>(ent, rel, norm, 0);
    gemm_kernel<<<GB, 256>>>(0, nullptr, 1);
    fixup_kernel<<<8, 256>>>(ent, Wa + 0 * WSTRIDE, nullptr, 1);

    // layer 1
    agg_kernel<<<AGB, 128>>>(nullptr, rel, norm, 1);
    gemm_kernel<<<GB, 256>>>(1, out, 0);
    fixup_kernel<<<8, 256>>>(nullptr, Wa + 1 * WSTRIDE, out, 0);
}

// round 9
// speedup vs baseline: 1.1542x; 1.1542x over previous
#include <cuda_runtime.h>
#include <cuda_bf16.h>

#define N_ENTS  50000
#define N_EDGES 500000
#define RANK    128
#define SLOPE   0.22916666666666666f   // (1/8 + 1/3)/2

typedef unsigned int u32;

// ---------------- device scratch (allocation-free rule) ----------------
// NOTE: __device__ globals are zero at module load; cleanup_kernel re-zeroes
// g_deg / g_deg0_count at the END of each launch so every graph replay starts
// from the same state (determinism).
__device__ int   g_deg[N_ENTS];
__device__ int   g_rowptr[N_ENTS + 1];
__device__ int   g_cursor[N_ENTS];
__device__ int   g_colsrc[N_EDGES];
__device__ int   g_colet[N_EDGES];
__device__ float g_h1[(size_t)N_ENTS * RANK];
__device__ float g_sumrel[(size_t)N_ENTS * RANK];
// A' bf16 [N_ENTS][256]: cols 0-127 = scaled agg, cols 128-255 = h
__device__ __nv_bfloat16 g_Ahi[(size_t)N_ENTS * 256];
__device__ __nv_bfloat16 g_Alo[(size_t)N_ENTS * 256];
// W' bf16 [layer][region hi/lo][n=128][k=256] (k contiguous; k<128: Wn, else Wl)
__device__ __nv_bfloat16 g_Wt[2 * 2 * 128 * 256];
__device__ int   g_deg0_list[N_ENTS];
__device__ int   g_deg0_count;

// ---------------- helpers ----------------
__device__ __forceinline__ u32 smem_u32(const void* p) {
    u32 a;
    asm("{ .reg .u64 t; cvta.to.shared.u64 t, %1; cvt.u32.u64 %0, t; }"
        : "=r"(a) : "l"(p));
    return a;
}
__device__ __forceinline__ void ldmx4(u32* r, u32 addr) {
    asm volatile("ldmatrix.sync.aligned.m8n8.x4.shared.b16 {%0,%1,%2,%3}, [%4];"
                 : "=r"(r[0]), "=r"(r[1]), "=r"(r[2]), "=r"(r[3]) : "r"(addr));
}
__device__ __forceinline__ void mma16816(float* c, const u32* a, const u32* b) {
    asm volatile(
        "mma.sync.aligned.m16n8k16.row.col.f32.bf16.bf16.f32 "
        "{%0,%1,%2,%3}, {%4,%5,%6,%7}, {%8,%9}, {%0,%1,%2,%3};"
        : "+f"(c[0]), "+f"(c[1]), "+f"(c[2]), "+f"(c[3])
        : "r"(a[0]), "r"(a[1]), "r"(a[2]), "r"(a[3]), "r"(b[0]), "r"(b[1]));
}
__device__ __forceinline__ void pack4(const float* v, uint2& uh, uint2& ul) {
    unsigned short hb[4], lb[4];
#pragma unroll
    for (int i = 0; i < 4; i++) {
        __nv_bfloat16 h = __float2bfloat16_rn(v[i]);
        __nv_bfloat16 l = __float2bfloat16_rn(v[i] - __bfloat162float(h));
        hb[i] = __bfloat16_as_ushort(h);
        lb[i] = __bfloat16_as_ushort(l);
    }
    uh.x = (u32)hb[0] | ((u32)hb[1] << 16);
    uh.y = (u32)hb[2] | ((u32)hb[3] << 16);
    ul.x = (u32)lb[0] | ((u32)lb[1] << 16);
    ul.y = (u32)lb[2] | ((u32)lb[3] << 16);
}

// ---------------- CSR build ----------------
__global__ void hist_kernel(const int* __restrict__ dst) {
    int e = blockIdx.x * blockDim.x + threadIdx.x;
    if (e < N_EDGES) atomicAdd(&g_deg[dst[e]], 1);
}

__global__ void scan_kernel() {
    __shared__ int sums[1024];
    const int CH = 49;
    int t = threadIdx.x;
    int start = t * CH;
    int end = start + CH; if (end > N_ENTS) end = N_ENTS;
    int s = 0;
    for (int i = start; i < end; i++) s += g_deg[i];
    sums[t] = s;
    __syncthreads();
    for (int off = 1; off < 1024; off <<= 1) {
        int v = (t >= off) ? sums[t - off] : 0;
        __syncthreads();
        sums[t] += v;
        __syncthreads();
    }
    int run = sums[t] - s;
    for (int i = start; i < end; i++) {
        g_rowptr[i] = run;
        g_cursor[i] = run;
        int d = g_deg[i];
        if (d == 0) {
            int p = atomicAdd(&g_deg0_count, 1);
            g_deg0_list[p] = i;
        }
        run += d;
    }
    if (t == 1023) g_rowptr[N_ENTS] = sums[1023];
}

__global__ void fill_kernel(const int* __restrict__ src, const int* __restrict__ dst,
                            const int* __restrict__ et) {
    int e = blockIdx.x * blockDim.x + threadIdx.x;
    if (e < N_EDGES) {
        int d = dst[e];
        int p = atomicAdd(&g_cursor[d], 1);
        g_colsrc[p] = src[e];
        g_colet[p]  = et[e];
    }
}

// tail: restore load-time state for next replay (g_deg=0, g_deg0_count=0)
__global__ void cleanup_kernel() {
    int i = blockIdx.x * blockDim.x + threadIdx.x;
    if (i < N_ENTS) g_deg[i] = 0;
    if (i == 0) g_deg0_count = 0;
}

// ---------------- prep: weight conversion + ent conversion (merged) -------
#define WTB  ((2 * 2 * 128 * 256 + 255) / 256)
#define ENTB ((N_ENTS * 32 + 255) / 256)
__global__ void prep_kernel(const float* __restrict__ Wn, const float* __restrict__ Wl,
                            const float* __restrict__ ent) {
    if (blockIdx.x < WTB) {
        int idx = blockIdx.x * blockDim.x + threadIdx.x;
        if (idx >= 2 * 2 * 128 * 256) return;
        int k = idx & 255;
        int n = (idx >> 8) & 127;
        int reg = (idx >> 15) & 1;
        int l = idx >> 16;
        const float* W = (k < 128) ? (Wn + l * 16384 + k * 128 + n)
                                   : (Wl + l * 16384 + (k - 128) * 128 + n);
        float v = *W;
        __nv_bfloat16 hi = __float2bfloat16_rn(v);
        __nv_bfloat16 o = reg ? __float2bfloat16_rn(v - __bfloat162float(hi)) : hi;
        g_Wt[idx] = o;
    } else {
        int idx = (blockIdx.x - WTB) * blockDim.x + threadIdx.x;
        if (idx >= N_ENTS * 32) return;
        int row = idx >> 5, q = idx & 31;
        float4 v = reinterpret_cast<const float4*>(ent + (size_t)row * RANK)[q];
        float f[4] = {v.x, v.y, v.z, v.w};
        uint2 uh, ul;
        pack4(f, uh, ul);
        *reinterpret_cast<uint2*>(g_Ahi + (size_t)row * 256 + 128 + q * 4) = uh;
        *reinterpret_cast<uint2*>(g_Alo + (size_t)row * 256 + 128 + q * 4) = ul;
    }
}

// ---------------- aggregation (R5-proven body) ----------------
// mode 0: gather h+rel, store sumrel, write bf16 agg (cols 0-127)
// mode 1: gather h only, add stored sumrel
__global__ void agg_kernel(const float* __restrict__ h_ext,
                           const float* __restrict__ rel,
                           const float* __restrict__ norm, int mode) {
    const float* __restrict__ h = h_ext ? h_ext : (const float*)g_h1;
    int w = (blockIdx.x * blockDim.x + threadIdx.x) >> 5;
    if (w >= N_ENTS) return;
    int lane = threadIdx.x & 31;
    int e0 = g_rowptr[w], e1 = g_rowptr[w + 1];

    float4 acc = make_float4(0.f, 0.f, 0.f, 0.f);
    float4 racc = make_float4(0.f, 0.f, 0.f, 0.f);
    for (int base = e0; base < e1; base += 32) {
        int mys = 0, myt = 0;
        if (base + lane < e1) { mys = g_colsrc[base + lane]; myt = g_colet[base + lane]; }
        int cnt = e1 - base; if (cnt > 32) cnt = 32;
        int j = 0;
        for (; j + 2 <= cnt; j += 2) {
            int s0 = __shfl_sync(0xffffffffu, mys, j);
            int s1 = __shfl_sync(0xffffffffu, mys, j + 1);
            float4 a0 = reinterpret_cast<const float4*>(h + (size_t)s0 * RANK)[lane];
            float4 a1 = reinterpret_cast<const float4*>(h + (size_t)s1 * RANK)[lane];
            acc.x += a0.x + a1.x; acc.y += a0.y + a1.y;
            acc.z += a0.z + a1.z; acc.w += a0.w + a1.w;
            if (mode == 0) {
                int t0 = __shfl_sync(0xffffffffu, myt, j);
                int t1 = __shfl_sync(0xffffffffu, myt, j + 1);
                float4 r0 = reinterpret_cast<const float4*>(rel + (size_t)t0 * RANK)[lane];
                float4 r1 = reinterpret_cast<const float4*>(rel + (size_t)t1 * RANK)[lane];
                racc.x += r0.x + r1.x; racc.y += r0.y + r1.y;
                racc.z += r0.z + r1.z; racc.w += r0.w + r1.w;
            }
        }
        for (; j < cnt; j++) {
            int s = __shfl_sync(0xffffffffu, mys, j);
            float4 a = reinterpret_cast<const float4*>(h + (size_t)s * RANK)[lane];
            acc.x += a.x; acc.y += a.y; acc.z += a.z; acc.w += a.w;
            if (mode == 0) {
                int t = __shfl_sync(0xffffffffu, myt, j);
                float4 r = reinterpret_cast<const float4*>(rel + (size_t)t * RANK)[lane];
                racc.x += r.x; racc.y += r.y; racc.z += r.z; racc.w += r.w;
            }
        }
    }
    if (mode == 0) {
        reinterpret_cast<float4*>(g_sumrel + (size_t)w * RANK)[lane] = racc;
    } else {
        racc = reinterpret_cast<const float4*>(g_sumrel + (size_t)w * RANK)[lane];
    }
    float nm = norm[w];
    float f[4] = {(acc.x + racc.x) * nm, (acc.y + racc.y) * nm,
                  (acc.z + racc.z) * nm, (acc.w + racc.w) * nm};
    uint2 uh, ul;
    pack4(f, uh, ul);
    *reinterpret_cast<uint2*>(g_Ahi + (size_t)w * 256 + lane * 4) = uh;
    *reinterpret_cast<uint2*>(g_Alo + (size_t)w * 256 + lane * 4) = ul;
}

// ---------------- bf16-split mma.sync GEMM (R5-proven) ----------------
__global__ void __launch_bounds__(256, 2)
gemm_kernel(int layer, float* __restrict__ out_ext, int write_bf16) {
    float* __restrict__ outf = out_ext ? out_ext : (float*)g_h1;

    __shared__ __align__(16) char sA[128 * 144];
    __shared__ __align__(16) char sB[128 * 144];

    const int tid = threadIdx.x;
    const int lane = tid & 31;
    const int wid = tid >> 5;
    const int warp_m = wid & 3;
    const int warp_n = wid >> 2;
    const int block_row = blockIdx.x * 128;

    const u32 sAu = smem_u32(sA);
    const u32 sBu = smem_u32(sB);

    const int a_q = lane >> 3;
    const int a_row = (lane & 7) + (a_q & 1) * 8;
    const int a_kb = (a_q >> 1) * 16;
    const int b_q = lane >> 3;
    const int b_row = ((b_q >> 1) * 8) + (lane & 7);
    const int b_kb = (b_q & 1) * 16;

    float c[2][8][4];
#pragma unroll
    for (int t = 0; t < 2; t++)
#pragma unroll
        for (int n = 0; n < 8; n++)
#pragma unroll
            for (int r = 0; r < 4; r++) c[t][n][r] = 0.f;

    for (int kc = 0; kc < 12; kc++) {
        const int pass = kc >> 2;
        const __nv_bfloat16* __restrict__ Asrc = (pass < 2) ? g_Ahi : g_Alo;
        const int region = (pass == 1) ? 1 : 0;
        const __nv_bfloat16* __restrict__ Bsrc =
            g_Wt + ((size_t)(layer * 2 + region) << 15);
        const int kcol = (kc & 3) * 64;

        __syncthreads();
#pragma unroll
        for (int i = 0; i < 4; i++) {
            int idx = tid + i * 256;
            int row = idx >> 3;
            int grp = (idx & 7) * 16;
            uint4 va = make_uint4(0u, 0u, 0u, 0u);
            int grow = block_row + row;
            if (grow < N_ENTS)
                va = *reinterpret_cast<const uint4*>(
                    reinterpret_cast<const char*>(Asrc + (size_t)grow * 256 + kcol) + grp);
            *reinterpret_cast<uint4*>(sA + row * 144 + grp) = va;
            uint4 vb = *reinterpret_cast<const uint4*>(
                reinterpret_cast<const char*>(Bsrc + (size_t)row * 256 + kcol) + grp);
            *reinterpret_cast<uint4*>(sB + row * 144 + grp) = vb;
        }
        __syncthreads();

#pragma unroll
        for (int j = 0; j < 4; j++) {
            u32 aa[2][4];
#pragma unroll
            for (int t = 0; t < 2; t++) {
                u32 addr = sAu + (warp_m * 32 + t * 16 + a_row) * 144 + j * 32 + a_kb;
                ldmx4(aa[t], addr);
            }
#pragma unroll
            for (int p = 0; p < 4; p++) {
                u32 bb[4];
                u32 addr = sBu + (warp_n * 64 + p * 16 + b_row) * 144 + j * 32 + b_kb;
                ldmx4(bb, addr);
#pragma unroll
                for (int t = 0; t < 2; t++) {
                    mma16816(c[t][2 * p],     aa[t], bb);
                    mma16816(c[t][2 * p + 1], aa[t], bb + 2);
                }
            }
        }
    }

    const int er = lane >> 2;
    const int ec = (lane & 3) * 2;
#pragma unroll
    for (int t = 0; t < 2; t++) {
#pragma unroll
        for (int half = 0; half < 2; half++) {
            int grow = block_row + warp_m * 32 + t * 16 + er + half * 8;
            if (grow >= N_ENTS) continue;
#pragma unroll
            for (int n = 0; n < 8; n++) {
                int col = warp_n * 64 + n * 8 + ec;
                float v0 = c[t][n][half * 2 + 0];
                float v1 = c[t][n][half * 2 + 1];
                v0 = (v0 >= 0.f) ? v0 : v0 * SLOPE;
                v1 = (v1 >= 0.f) ? v1 : v1 * SLOPE;
                *reinterpret_cast<float2*>(outf + (size_t)grow * RANK + col) =
                    make_float2(v0, v1);
                if (write_bf16) {
                    __nv_bfloat16 h0 = __float2bfloat16_rn(v0);
                    __nv_bfloat16 h1 = __float2bfloat16_rn(v1);
                    __nv_bfloat16 l0 = __float2bfloat16_rn(v0 - __bfloat162float(h0));
                    __nv_bfloat16 l1 = __float2bfloat16_rn(v1 - __bfloat162float(h1));
                    u32 ph = (u32)__bfloat16_as_ushort(h0) |
                             ((u32)__bfloat16_as_ushort(h1) << 16);
                    u32 pl = (u32)__bfloat16_as_ushort(l0) |
                             ((u32)__bfloat16_as_ushort(l1) << 16);
                    *reinterpret_cast<u32*>(g_Ahi + (size_t)grow * 256 + 128 + col) = ph;
                    *reinterpret_cast<u32*>(g_Alo + (size_t)grow * 256 + 128 + col) = pl;
                }
            }
        }
    }
}

// ---------------- deg-0 fixup ----------------
__global__ void fixup_kernel(const float* __restrict__ h_ext,
                             const float* __restrict__ Wa,
                             float* __restrict__ out_ext, int write_bf16) {
    const float* __restrict__ h = h_ext ? h_ext : (const float*)g_h1;
    float* __restrict__ Out = out_ext ? out_ext : (float*)g_h1;
    int wg = (blockIdx.x * blockDim.x + threadIdx.x) >> 5;
    int lane = threadIdx.x & 31;
    int nwarp = (gridDim.x * blockDim.x) >> 5;
    int cnt = g_deg0_count;
    for (int idx = wg; idx < cnt; idx += nwarp) {
        int v = g_deg0_list[idx];
        const float* hr = h + (size_t)v * RANK;
        float4 acc = make_float4(0.f, 0.f, 0.f, 0.f);
        for (int k = 0; k < RANK; k++) {
            float a = hr[k];
            float4 wv = reinterpret_cast<const float4*>(Wa + (size_t)k * RANK)[lane];
            acc.x += a * wv.x; acc.y += a * wv.y;
            acc.z += a * wv.z; acc.w += a * wv.w;
        }
        float f[4];
        f[0] = (acc.x >= 0.f) ? acc.x : acc.x * SLOPE;
        f[1] = (acc.y >= 0.f) ? acc.y : acc.y * SLOPE;
        f[2] = (acc.z >= 0.f) ? acc.z : acc.z * SLOPE;
        f[3] = (acc.w >= 0.f) ? acc.w : acc.w * SLOPE;
        reinterpret_cast<float4*>(Out + (size_t)v * RANK)[lane] =
            make_float4(f[0], f[1], f[2], f[3]);
        if (write_bf16) {
            uint2 uh, ul;
            pack4(f, uh, ul);
            *reinterpret_cast<uint2*>(g_Ahi + (size_t)v * 256 + 128 + lane * 4) = uh;
            *reinterpret_cast<uint2*>(g_Alo + (size_t)v * 256 + 128 + lane * 4) = ul;
        }
    }
}

// ---------------- launch ----------------
extern "C" void kernel_launch(void* const* d_in, const int* in_sizes, int n_in,
                              void* d_out, int out_size) {
    const float* ent  = (const float*)d_in[0];
    const float* rel  = (const float*)d_in[1];
    const float* norm = (const float*)d_in[2];
    const float* Wn   = (const float*)d_in[3];
    const float* Wl   = (const float*)d_in[4];
    const float* Wa   = (const float*)d_in[5];
    const int*   src  = (const int*)d_in[6];
    const int*   dst  = (const int*)d_in[7];
    const int*   et   = (const int*)d_in[8];
    float* out = (float*)d_out;

    const int NB  = (N_ENTS + 255) / 256;
    const int EB  = (N_EDGES + 255) / 256;
    const int AGB = (N_ENTS * 32 + 255) / 256;
    const int GB  = (N_ENTS + 127) / 128;
    const int WSTRIDE = RANK * RANK;

    // g_deg / g_deg0_count are zero at entry (BSS at load; cleanup at tail).
    hist_kernel<<<EB, 256>>>(dst);                     // 1
    scan_kernel<<<1, 1024>>>();                        // 2
    fill_kernel<<<EB, 256>>>(src, dst, et);            // 3
    agg_kernel<<<AGB, 256>>>(ent, rel, norm, 0);       // 4  <-- ncu capture slot
    prep_kernel<<<WTB + ENTB, 256>>>(Wn, Wl, ent);     // 5
    gemm_kernel<<<GB, 256>>>(0, nullptr, 1);           // 6
    fixup_kernel<<<8, 256>>>(ent, Wa + 0 * WSTRIDE, nullptr, 1);   // 7
    agg_kernel<<<AGB, 256>>>(nullptr, rel, norm, 1);   // 8
    gemm_kernel<<<GB, 256>>>(1, out, 0);               // 9
    fixup_kernel<<<8, 256>>>(nullptr, Wa + 1 * WSTRIDE, out, 0);   // 10
    cleanup_kernel<<<NB, 256>>>();                     // 11 (restore state)
}

// round 10
// speedup vs baseline: 1.1905x; 1.0314x over previous
#include <cuda_runtime.h>
#include <cuda_bf16.h>

#define N_ENTS  50000
#define N_EDGES 500000
#define RANK    128
#define SLOPE   0.22916666666666666f   // (1/8 + 1/3)/2

typedef unsigned int u32;

// ---------------- device scratch (allocation-free rule) ----------------
// __device__ globals are zero at module load; cleanup_kernel re-zeroes
// g_deg / g_deg0_count at the END of each launch (replay determinism).
__device__ int   g_deg[N_ENTS];
__device__ int   g_rowptr[N_ENTS + 1];
__device__ int   g_cursor[N_ENTS];
__device__ int   g_colsrc[N_EDGES];
__device__ int   g_colet[N_EDGES];
__device__ float g_h1[(size_t)N_ENTS * RANK];
__device__ float g_sumrel[(size_t)N_ENTS * RANK];
// A' bf16 [N_ENTS][256]: cols 0-127 = scaled agg, cols 128-255 = h
__device__ __nv_bfloat16 g_Ahi[(size_t)N_ENTS * 256];
__device__ __nv_bfloat16 g_Alo[(size_t)N_ENTS * 256];
// W' bf16 [layer][region hi/lo][n=128][k=256]
__device__ __nv_bfloat16 g_Wt[2 * 2 * 128 * 256];
__device__ int   g_deg0_list[N_ENTS];
__device__ int   g_deg0_count;

// ---------------- helpers ----------------
__device__ __forceinline__ u32 smem_u32(const void* p) {
    u32 a;
    asm("{ .reg .u64 t; cvta.to.shared.u64 t, %1; cvt.u32.u64 %0, t; }"
        : "=r"(a) : "l"(p));
    return a;
}
__device__ __forceinline__ void cpa16z(u32 saddr, const void* g, int sz) {
    asm volatile("cp.async.ca.shared.global [%0], [%1], 16, %2;"
                 :: "r"(saddr), "l"(g), "r"(sz) : "memory");
}
__device__ __forceinline__ void cpa_commit() {
    asm volatile("cp.async.commit_group;" ::: "memory");
}
__device__ __forceinline__ void cpa_wait1() {
    asm volatile("cp.async.wait_group 1;" ::: "memory");
}
__device__ __forceinline__ void ldmx4(u32* r, u32 addr) {
    asm volatile("ldmatrix.sync.aligned.m8n8.x4.shared.b16 {%0,%1,%2,%3}, [%4];"
                 : "=r"(r[0]), "=r"(r[1]), "=r"(r[2]), "=r"(r[3]) : "r"(addr));
}
__device__ __forceinline__ void mma16816(float* c, const u32* a, const u32* b) {
    asm volatile(
        "mma.sync.aligned.m16n8k16.row.col.f32.bf16.bf16.f32 "
        "{%0,%1,%2,%3}, {%4,%5,%6,%7}, {%8,%9}, {%0,%1,%2,%3};"
        : "+f"(c[0]), "+f"(c[1]), "+f"(c[2]), "+f"(c[3])
        : "r"(a[0]), "r"(a[1]), "r"(a[2]), "r"(a[3]), "r"(b[0]), "r"(b[1]));
}
__device__ __forceinline__ void pack4(const float* v, uint2& uh, uint2& ul) {
    unsigned short hb[4], lb[4];
#pragma unroll
    for (int i = 0; i < 4; i++) {
        __nv_bfloat16 h = __float2bfloat16_rn(v[i]);
        __nv_bfloat16 l = __float2bfloat16_rn(v[i] - __bfloat162float(h));
        hb[i] = __bfloat16_as_ushort(h);
        lb[i] = __bfloat16_as_ushort(l);
    }
    uh.x = (u32)hb[0] | ((u32)hb[1] << 16);
    uh.y = (u32)hb[2] | ((u32)hb[3] << 16);
    ul.x = (u32)lb[0] | ((u32)lb[1] << 16);
    ul.y = (u32)lb[2] | ((u32)lb[3] << 16);
}

// ---------------- CSR build ----------------
__global__ void hist_kernel(const int* __restrict__ dst) {
    int e = blockIdx.x * blockDim.x + threadIdx.x;
    if (e < N_EDGES) atomicAdd(&g_deg[dst[e]], 1);
}

__global__ void scan_kernel() {
    __shared__ int sums[1024];
    const int CH = 49;
    int t = threadIdx.x;
    int start = t * CH;
    int end = start + CH; if (end > N_ENTS) end = N_ENTS;
    int s = 0;
    for (int i = start; i < end; i++) s += g_deg[i];
    sums[t] = s;
    __syncthreads();
    for (int off = 1; off < 1024; off <<= 1) {
        int v = (t >= off) ? sums[t - off] : 0;
        __syncthreads();
        sums[t] += v;
        __syncthreads();
    }
    int run = sums[t] - s;
    for (int i = start; i < end; i++) {
        g_rowptr[i] = run;
        g_cursor[i] = run;
        int d = g_deg[i];
        if (d == 0) {
            int p = atomicAdd(&g_deg0_count, 1);
            g_deg0_list[p] = i;
        }
        run += d;
    }
    if (t == 1023) g_rowptr[N_ENTS] = sums[1023];
}

__global__ void fill_kernel(const int* __restrict__ src, const int* __restrict__ dst,
                            const int* __restrict__ et) {
    int e = blockIdx.x * blockDim.x + threadIdx.x;
    if (e < N_EDGES) {
        int d = dst[e];
        int p = atomicAdd(&g_cursor[d], 1);
        g_colsrc[p] = src[e];
        g_colet[p]  = et[e];
    }
}

__global__ void cleanup_kernel() {
    int i = blockIdx.x * blockDim.x + threadIdx.x;
    if (i < N_ENTS) g_deg[i] = 0;
    if (i == 0) g_deg0_count = 0;
}

// ---------------- prep: weight conversion + ent conversion (merged) -------
#define WTB  ((2 * 2 * 128 * 256 + 255) / 256)
#define ENTB ((N_ENTS * 32 + 255) / 256)
__global__ void prep_kernel(const float* __restrict__ Wn, const float* __restrict__ Wl,
                            const float* __restrict__ ent) {
    if (blockIdx.x < WTB) {
        int idx = blockIdx.x * blockDim.x + threadIdx.x;
        if (idx >= 2 * 2 * 128 * 256) return;
        int k = idx & 255;
        int n = (idx >> 8) & 127;
        int reg = (idx >> 15) & 1;
        int l = idx >> 16;
        const float* W = (k < 128) ? (Wn + l * 16384 + k * 128 + n)
                                   : (Wl + l * 16384 + (k - 128) * 128 + n);
        float v = *W;
        __nv_bfloat16 hi = __float2bfloat16_rn(v);
        __nv_bfloat16 o = reg ? __float2bfloat16_rn(v - __bfloat162float(hi)) : hi;
        g_Wt[idx] = o;
    } else {
        int idx = (blockIdx.x - WTB) * blockDim.x + threadIdx.x;
        if (idx >= N_ENTS * 32) return;
        int row = idx >> 5, q = idx & 31;
        float4 v = reinterpret_cast<const float4*>(ent + (size_t)row * RANK)[q];
        float f[4] = {v.x, v.y, v.z, v.w};
        uint2 uh, ul;
        pack4(f, uh, ul);
        *reinterpret_cast<uint2*>(g_Ahi + (size_t)row * 256 + 128 + q * 4) = uh;
        *reinterpret_cast<uint2*>(g_Alo + (size_t)row * 256 + 128 + q * 4) = ul;
    }
}

// ---------------- aggregation (R5/R9-proven body) ----------------
__global__ void agg_kernel(const float* __restrict__ h_ext,
                           const float* __restrict__ rel,
                           const float* __restrict__ norm, int mode) {
    const float* __restrict__ h = h_ext ? h_ext : (const float*)g_h1;
    int w = (blockIdx.x * blockDim.x + threadIdx.x) >> 5;
    if (w >= N_ENTS) return;
    int lane = threadIdx.x & 31;
    int e0 = g_rowptr[w], e1 = g_rowptr[w + 1];

    float4 acc = make_float4(0.f, 0.f, 0.f, 0.f);
    float4 racc = make_float4(0.f, 0.f, 0.f, 0.f);
    for (int base = e0; base < e1; base += 32) {
        int mys = 0, myt = 0;
        if (base + lane < e1) { mys = g_colsrc[base + lane]; myt = g_colet[base + lane]; }
        int cnt = e1 - base; if (cnt > 32) cnt = 32;
        int j = 0;
        for (; j + 2 <= cnt; j += 2) {
            int s0 = __shfl_sync(0xffffffffu, mys, j);
            int s1 = __shfl_sync(0xffffffffu, mys, j + 1);
            float4 a0 = reinterpret_cast<const float4*>(h + (size_t)s0 * RANK)[lane];
            float4 a1 = reinterpret_cast<const float4*>(h + (size_t)s1 * RANK)[lane];
            acc.x += a0.x + a1.x; acc.y += a0.y + a1.y;
            acc.z += a0.z + a1.z; acc.w += a0.w + a1.w;
            if (mode == 0) {
                int t0 = __shfl_sync(0xffffffffu, myt, j);
                int t1 = __shfl_sync(0xffffffffu, myt, j + 1);
                float4 r0 = reinterpret_cast<const float4*>(rel + (size_t)t0 * RANK)[lane];
                float4 r1 = reinterpret_cast<const float4*>(rel + (size_t)t1 * RANK)[lane];
                racc.x += r0.x + r1.x; racc.y += r0.y + r1.y;
                racc.z += r0.z + r1.z; racc.w += r0.w + r1.w;
            }
        }
        for (; j < cnt; j++) {
            int s = __shfl_sync(0xffffffffu, mys, j);
            float4 a = reinterpret_cast<const float4*>(h + (size_t)s * RANK)[lane];
            acc.x += a.x; acc.y += a.y; acc.z += a.z; acc.w += a.w;
            if (mode == 0) {
                int t = __shfl_sync(0xffffffffu, myt, j);
                float4 r = reinterpret_cast<const float4*>(rel + (size_t)t * RANK)[lane];
                racc.x += r.x; racc.y += r.y; racc.z += r.z; racc.w += r.w;
            }
        }
    }
    if (mode == 0) {
        reinterpret_cast<float4*>(g_sumrel + (size_t)w * RANK)[lane] = racc;
    } else {
        racc = reinterpret_cast<const float4*>(g_sumrel + (size_t)w * RANK)[lane];
    }
    float nm = norm[w];
    float f[4] = {(acc.x + racc.x) * nm, (acc.y + racc.y) * nm,
                  (acc.z + racc.z) * nm, (acc.w + racc.w) * nm};
    uint2 uh, ul;
    pack4(f, uh, ul);
    *reinterpret_cast<uint2*>(g_Ahi + (size_t)w * 256 + lane * 4) = uh;
    *reinterpret_cast<uint2*>(g_Alo + (size_t)w * 256 + lane * 4) = ul;
}

// ---------------- bf16-split mma.sync GEMM, cp.async double-buffered ------
// BK=32: 24 chunks over 3 passes (Ahi*Whi, Ahi*Wlo, Alo*Whi).
// Tiles: 128 rows x 32 bf16 (64B data), row stride 80B (conflict-free ldmatrix).
#define NCH   24
#define TROWB 80
#define TILEB (128 * TROWB)
__global__ void __launch_bounds__(256, 2)
gemm_kernel(int layer, float* __restrict__ out_ext, int write_bf16) {
    float* __restrict__ outf = out_ext ? out_ext : (float*)g_h1;

    __shared__ __align__(16) char sA[2][TILEB];
    __shared__ __align__(16) char sB[2][TILEB];

    const int tid = threadIdx.x;
    const int lane = tid & 31;
    const int wid = tid >> 5;
    const int warp_m = wid & 3;
    const int warp_n = wid >> 2;
    const int block_row = blockIdx.x * 128;

    const u32 sAu = smem_u32(sA);
    const u32 sBu = smem_u32(sB);

    // loader indexing: 512 x 16B per tile; e = tid + i*256
    const int l_row0 = tid >> 2;          // e>>2 for i=0 (rows 0..63)
    const int l_c16  = (tid & 3) * 16;    // byte within 64B row data

    const int a_q = lane >> 3;
    const int a_row = (lane & 7) + (a_q & 1) * 8;
    const int a_kb = (a_q >> 1) * 16;
    const int b_q = lane >> 3;
    const int b_row = ((b_q >> 1) * 8) + (lane & 7);
    const int b_kb = (b_q & 1) * 16;

    float c[2][8][4];
#pragma unroll
    for (int t = 0; t < 2; t++)
#pragma unroll
        for (int n = 0; n < 8; n++)
#pragma unroll
            for (int r = 0; r < 4; r++) c[t][n][r] = 0.f;

    const __nv_bfloat16* __restrict__ WtL = g_Wt + ((size_t)layer << 16);

    // stage issue: chunk kc into buffer buf
    auto issue = [&](int kc, int buf) {
        const int pass = kc >> 3;                       // 0,1,2
        const __nv_bfloat16* Asrc = (pass < 2) ? g_Ahi : g_Alo;
        const __nv_bfloat16* Bsrc = WtL + ((pass == 1) ? (1 << 15) : 0);
        const int kbyte = (kc & 7) * 64;                // 32 cols * 2B
#pragma unroll
        for (int i = 0; i < 2; i++) {
            int row = l_row0 + i * 64;
            int grow = block_row + row;
            u32 sa = sAu + buf * TILEB + row * TROWB + l_c16;
            cpa16z(sa, (const char*)Asrc + (size_t)grow * 512 + kbyte + l_c16,
                   (grow < N_ENTS) ? 16 : 0);
            u32 sb = sBu + buf * TILEB + row * TROWB + l_c16;
            cpa16z(sb, (const char*)Bsrc + (size_t)row * 512 + kbyte + l_c16, 16);
        }
    };

    issue(0, 0); cpa_commit();
    issue(1, 1); cpa_commit();

    for (int kc = 0; kc < NCH; kc++) {
        const int buf = kc & 1;
        cpa_wait1();
        __syncthreads();
        const u32 aBase = sAu + buf * TILEB;
        const u32 bBase = sBu + buf * TILEB;
#pragma unroll
        for (int j = 0; j < 2; j++) {
            u32 aa[2][4];
#pragma unroll
            for (int t = 0; t < 2; t++)
                ldmx4(aa[t], aBase + (warp_m * 32 + t * 16 + a_row) * TROWB + j * 32 + a_kb);
#pragma unroll
            for (int p = 0; p < 4; p++) {
                u32 bb[4];
                ldmx4(bb, bBase + (warp_n * 64 + p * 16 + b_row) * TROWB + j * 32 + b_kb);
#pragma unroll
                for (int t = 0; t < 2; t++) {
                    mma16816(c[t][2 * p],     aa[t], bb);
                    mma16816(c[t][2 * p + 1], aa[t], bb + 2);
                }
            }
        }
        __syncthreads();
        if (kc + 2 < NCH) issue(kc + 2, buf);
        cpa_commit();
    }

    // epilogue: leaky relu, write fp32 (+ bf16 hi/lo h-part for next layer)
    const int er = lane >> 2;
    const int ec = (lane & 3) * 2;
#pragma unroll
    for (int t = 0; t < 2; t++) {
#pragma unroll
        for (int half = 0; half < 2; half++) {
            int grow = block_row + warp_m * 32 + t * 16 + er + half * 8;
            if (grow >= N_ENTS) continue;
#pragma unroll
            for (int n = 0; n < 8; n++) {
                int col = warp_n * 64 + n * 8 + ec;
                float v0 = c[t][n][half * 2 + 0];
                float v1 = c[t][n][half * 2 + 1];
                v0 = (v0 >= 0.f) ? v0 : v0 * SLOPE;
                v1 = (v1 >= 0.f) ? v1 : v1 * SLOPE;
                *reinterpret_cast<float2*>(outf + (size_t)grow * RANK + col) =
                    make_float2(v0, v1);
                if (write_bf16) {
                    __nv_bfloat16 h0 = __float2bfloat16_rn(v0);
                    __nv_bfloat16 h1 = __float2bfloat16_rn(v1);
                    __nv_bfloat16 l0 = __float2bfloat16_rn(v0 - __bfloat162float(h0));
                    __nv_bfloat16 l1 = __float2bfloat16_rn(v1 - __bfloat162float(h1));
                    u32 ph = (u32)__bfloat16_as_ushort(h0) |
                             ((u32)__bfloat16_as_ushort(h1) << 16);
                    u32 pl = (u32)__bfloat16_as_ushort(l0) |
                             ((u32)__bfloat16_as_ushort(l1) << 16);
                    *reinterpret_cast<u32*>(g_Ahi + (size_t)grow * 256 + 128 + col) = ph;
                    *reinterpret_cast<u32*>(g_Alo + (size_t)grow * 256 + 128 + col) = pl;
                }
            }
        }
    }
}

// ---------------- deg-0 fixup ----------------
__global__ void fixup_kernel(const float* __restrict__ h_ext,
                             const float* __restrict__ Wa,
                             float* __restrict__ out_ext, int write_bf16) {
    const float* __restrict__ h = h_ext ? h_ext : (const float*)g_h1;
    float* __restrict__ Out = out_ext ? out_ext : (float*)g_h1;
    int wg = (blockIdx.x * blockDim.x + threadIdx.x) >> 5;
    int lane = threadIdx.x & 31;
    int nwarp = (gridDim.x * blockDim.x) >> 5;
    int cnt = g_deg0_count;
    for (int idx = wg; idx < cnt; idx += nwarp) {
        int v = g_deg0_list[idx];
        const float* hr = h + (size_t)v * RANK;
        float4 acc = make_float4(0.f, 0.f, 0.f, 0.f);
        for (int k = 0; k < RANK; k++) {
            float a = hr[k];
            float4 wv = reinterpret_cast<const float4*>(Wa + (size_t)k * RANK)[lane];
            acc.x += a * wv.x; acc.y += a * wv.y;
            acc.z += a * wv.z; acc.w += a * wv.w;
        }
        float f[4];
        f[0] = (acc.x >= 0.f) ? acc.x : acc.x * SLOPE;
        f[1] = (acc.y >= 0.f) ? acc.y : acc.y * SLOPE;
        f[2] = (acc.z >= 0.f) ? acc.z : acc.z * SLOPE;
        f[3] = (acc.w >= 0.f) ? acc.w : acc.w * SLOPE;
        reinterpret_cast<float4*>(Out + (size_t)v * RANK)[lane] =
            make_float4(f[0], f[1], f[2], f[3]);
        if (write_bf16) {
            uint2 uh, ul;
            pack4(f, uh, ul);
            *reinterpret_cast<uint2*>(g_Ahi + (size_t)v * 256 + 128 + lane * 4) = uh;
            *reinterpret_cast<uint2*>(g_Alo + (size_t)v * 256 + 128 + lane * 4) = ul;
        }
    }
}

// ---------------- launch ----------------
extern "C" void kernel_launch(void* const* d_in, const int* in_sizes, int n_in,
                              void* d_out, int out_size) {
    const float* ent  = (const float*)d_in[0];
    const float* rel  = (const float*)d_in[1];
    const float* norm = (const float*)d_in[2];
    const float* Wn   = (const float*)d_in[3];
    const float* Wl   = (const float*)d_in[4];
    const float* Wa   = (const float*)d_in[5];
    const int*   src  = (const int*)d_in[6];
    const int*   dst  = (const int*)d_in[7];
    const int*   et   = (const int*)d_in[8];
    float* out = (float*)d_out;

    const int NB  = (N_ENTS + 255) / 256;
    const int EB  = (N_EDGES + 255) / 256;
    const int AGB = (N_ENTS * 32 + 255) / 256;
    const int GB  = (N_ENTS + 127) / 128;
    const int WSTRIDE = RANK * RANK;

    hist_kernel<<<EB, 256>>>(dst);                     // 1
    scan_kernel<<<1, 1024>>>();                        // 2
    fill_kernel<<<EB, 256>>>(src, dst, et);            // 3
    agg_kernel<<<AGB, 256>>>(ent, rel, norm, 0);       // 4  <-- ncu capture slot
    prep_kernel<<<WTB + ENTB, 256>>>(Wn, Wl, ent);     // 5
    gemm_kernel<<<GB, 256>>>(0, nullptr, 1);           // 6
    fixup_kernel<<<8, 256>>>(ent, Wa + 0 * WSTRIDE, nullptr, 1);   // 7
    agg_kernel<<<AGB, 256>>>(nullptr, rel, norm, 1);   // 8
    gemm_kernel<<<GB, 256>>>(1, out, 0);               // 9
    fixup_kernel<<<8, 256>>>(nullptr, Wa + 1 * WSTRIDE, out, 0);   // 10
    cleanup_kernel<<<NB, 256>>>();                     // 11
}

// round 11
// speedup vs baseline: 2.0163x; 1.6937x over previous
#include <cuda_runtime.h>
#include <cuda_fp16.h>

#define N_ENTS  50000
#define N_EDGES 500000
#define RANK    128
#define SLOPE   0.22916666666666666f   // (1/8 + 1/3)/2

typedef unsigned int u32;

// ---------------- device scratch (allocation-free rule) ----------------
// g_deg zeroed by scanC at end-of-use; g_deg0_count zeroed by fixup1 (tail).
__device__ int   g_deg[N_ENTS];
__device__ int   g_rowptr[N_ENTS + 1];
__device__ int   g_cursor[N_ENTS];
__device__ int2  g_coledge[N_EDGES];          // (src, etype) per CSR slot
__device__ float g_h1[(size_t)N_ENTS * RANK];
__device__ float g_sumrel[(size_t)N_ENTS * RANK];
// A fp16 [N_ENTS][256]: cols 0-127 = scaled agg, cols 128-255 = h
__device__ __half g_Af[(size_t)N_ENTS * 256];
// W fp16 [layer][n=128][k=256]: hi part and residual part (k<128: Wn, else Wl)
__device__ __half g_Wh[2 * 128 * 256];
__device__ __half g_Wr[2 * 128 * 256];
__device__ int   g_deg0_list[N_ENTS];
__device__ int   g_deg0_count;
#define SNB 49                                 // ceil(50000/1024)
__device__ int   g_bsum[SNB];
__device__ int   g_boff[SNB];

// ---------------- helpers ----------------
__device__ __forceinline__ u32 smem_u32(const void* p) {
    u32 a;
    asm("{ .reg .u64 t; cvta.to.shared.u64 t, %1; cvt.u32.u64 %0, t; }"
        : "=r"(a) : "l"(p));
    return a;
}
__device__ __forceinline__ void cpa16z(u32 saddr, const void* g, int sz) {
    asm volatile("cp.async.ca.shared.global [%0], [%1], 16, %2;"
                 :: "r"(saddr), "l"(g), "r"(sz) : "memory");
}
__device__ __forceinline__ void cpa16(u32 saddr, const void* g) {
    asm volatile("cp.async.ca.shared.global [%0], [%1], 16;"
                 :: "r"(saddr), "l"(g) : "memory");
}
__device__ __forceinline__ void cpa_commit() {
    asm volatile("cp.async.commit_group;" ::: "memory");
}
__device__ __forceinline__ void cpa_wait1() {
    asm volatile("cp.async.wait_group 1;" ::: "memory");
}
__device__ __forceinline__ void ldmx4(u32* r, u32 addr) {
    asm volatile("ldmatrix.sync.aligned.m8n8.x4.shared.b16 {%0,%1,%2,%3}, [%4];"
                 : "=r"(r[0]), "=r"(r[1]), "=r"(r[2]), "=r"(r[3]) : "r"(addr));
}
__device__ __forceinline__ void mma16816h(float* c, const u32* a, const u32* b) {
    asm volatile(
        "mma.sync.aligned.m16n8k16.row.col.f32.f16.f16.f32 "
        "{%0,%1,%2,%3}, {%4,%5,%6,%7}, {%8,%9}, {%0,%1,%2,%3};"
        : "+f"(c[0]), "+f"(c[1]), "+f"(c[2]), "+f"(c[3])
        : "r"(a[0]), "r"(a[1]), "r"(a[2]), "r"(a[3]), "r"(b[0]), "r"(b[1]));
}
__device__ __forceinline__ u32 h2u(__half2 h) {
    return *reinterpret_cast<u32*>(&h);
}

// ---------------- CSR build ----------------
__global__ void hist_kernel(const int* __restrict__ dst) {
    int e = blockIdx.x * blockDim.x + threadIdx.x;
    if (e < N_EDGES) atomicAdd(&g_deg[dst[e]], 1);
}

__global__ void scanA_kernel() {          // grid SNB x 1024: block sums
    __shared__ int red[1024];
    int i = blockIdx.x * 1024 + threadIdx.x;
    int d = (i < N_ENTS) ? g_deg[i] : 0;
    red[threadIdx.x] = d;
    __syncthreads();
    for (int off = 512; off > 0; off >>= 1) {
        if (threadIdx.x < off) red[threadIdx.x] += red[threadIdx.x + off];
        __syncthreads();
    }
    if (threadIdx.x == 0) g_bsum[blockIdx.x] = red[0];
}

__global__ void scanB_kernel() {          // 1 x 64: exclusive scan of block sums
    __shared__ int s[64];
    int t = threadIdx.x;
    int d = (t < SNB) ? g_bsum[t] : 0;
    s[t] = d;
    __syncthreads();
    for (int off = 1; off < 64; off <<= 1) {
        int v = (t >= off) ? s[t - off] : 0;
        __syncthreads();
        s[t] += v;
        __syncthreads();
    }
    if (t < SNB) g_boff[t] = s[t] - d;
}

__global__ void scanC_kernel() {          // grid SNB x 1024: rowptr/cursor + deg0 + reset
    __shared__ int s[1024];
    int tid = threadIdx.x;
    int i = blockIdx.x * 1024 + tid;
    int d = (i < N_ENTS) ? g_deg[i] : 0;
    s[tid] = d;
    __syncthreads();
    for (int off = 1; off < 1024; off <<= 1) {
        int v = (tid >= off) ? s[tid - off] : 0;
        __syncthreads();
        s[tid] += v;
        __syncthreads();
    }
    if (i < N_ENTS) {
        int excl = s[tid] - d + g_boff[blockIdx.x];
        g_rowptr[i] = excl;
        g_cursor[i] = excl;
        if (d == 0) {
            int p = atomicAdd(&g_deg0_count, 1);
            g_deg0_list[p] = i;
        }
        g_deg[i] = 0;                      // reset for next replay
    }
    if (i == 0) g_rowptr[N_ENTS] = N_EDGES;
}

__global__ void fill_kernel(const int* __restrict__ src, const int* __restrict__ dst,
                            const int* __restrict__ et) {
    int e = blockIdx.x * blockDim.x + threadIdx.x;
    if (e < N_EDGES) {
        int d = dst[e];
        int p = atomicAdd(&g_cursor[d], 1);
        g_coledge[p] = make_int2(src[e], et[e]);
    }
}

// ---------------- prep: weight split + ent conversion ----------------
#define WTB  (2 * 128 * 256 / 256)                 // 256 blocks
#define ENTB ((N_ENTS * 32 + 255) / 256)
__global__ void prep_kernel(const float* __restrict__ Wn, const float* __restrict__ Wl,
                            const float* __restrict__ ent) {
    if (blockIdx.x < WTB) {
        int idx = blockIdx.x * blockDim.x + threadIdx.x;   // [l][n][k]
        int k = idx & 255;
        int n = (idx >> 8) & 127;
        int l = idx >> 15;
        const float* W = (k < 128) ? (Wn + l * 16384 + k * 128 + n)
                                   : (Wl + l * 16384 + (k - 128) * 128 + n);
        float v = *W;
        __half hi = __float2half_rn(v);
        __half lo = __float2half_rn(v - __half2float(hi));
        g_Wh[idx] = hi;
        g_Wr[idx] = lo;
    } else {
        int idx = (blockIdx.x - WTB) * blockDim.x + threadIdx.x;
        if (idx >= N_ENTS * 32) return;
        int row = idx >> 5, q = idx & 31;
        float4 v = reinterpret_cast<const float4*>(ent + (size_t)row * RANK)[q];
        uint2 o;
        o.x = h2u(__floats2half2_rn(v.x, v.y));
        o.y = h2u(__floats2half2_rn(v.z, v.w));
        *reinterpret_cast<uint2*>(g_Af + (size_t)row * 256 + 128 + q * 4) = o;
    }
}

// ---------------- aggregation (R5/R9-proven body, fp16 out) ----------------
__global__ void agg_kernel(const float* __restrict__ h_ext,
                           const float* __restrict__ rel,
                           const float* __restrict__ norm, int mode) {
    const float* __restrict__ h = h_ext ? h_ext : (const float*)g_h1;
    int w = (blockIdx.x * blockDim.x + threadIdx.x) >> 5;
    if (w >= N_ENTS) return;
    int lane = threadIdx.x & 31;
    int e0 = g_rowptr[w], e1 = g_rowptr[w + 1];

    float4 acc = make_float4(0.f, 0.f, 0.f, 0.f);
    float4 racc = make_float4(0.f, 0.f, 0.f, 0.f);
    for (int base = e0; base < e1; base += 32) {
        int mys = 0, myt = 0;
        if (base + lane < e1) {
            int2 ed = g_coledge[base + lane];
            mys = ed.x; myt = ed.y;
        }
        int cnt = e1 - base; if (cnt > 32) cnt = 32;
        int j = 0;
        for (; j + 2 <= cnt; j += 2) {
            int s0 = __shfl_sync(0xffffffffu, mys, j);
            int s1 = __shfl_sync(0xffffffffu, mys, j + 1);
            float4 a0 = reinterpret_cast<const float4*>(h + (size_t)s0 * RANK)[lane];
            float4 a1 = reinterpret_cast<const float4*>(h + (size_t)s1 * RANK)[lane];
            acc.x += a0.x + a1.x; acc.y += a0.y + a1.y;
            acc.z += a0.z + a1.z; acc.w += a0.w + a1.w;
            if (mode == 0) {
                int t0 = __shfl_sync(0xffffffffu, myt, j);
                int t1 = __shfl_sync(0xffffffffu, myt, j + 1);
                float4 r0 = reinterpret_cast<const float4*>(rel + (size_t)t0 * RANK)[lane];
                float4 r1 = reinterpret_cast<const float4*>(rel + (size_t)t1 * RANK)[lane];
                racc.x += r0.x + r1.x; racc.y += r0.y + r1.y;
                racc.z += r0.z + r1.z; racc.w += r0.w + r1.w;
            }
        }
        for (; j < cnt; j++) {
            int s = __shfl_sync(0xffffffffu, mys, j);
            float4 a = reinterpret_cast<const float4*>(h + (size_t)s * RANK)[lane];
            acc.x += a.x; acc.y += a.y; acc.z += a.z; acc.w += a.w;
            if (mode == 0) {
                int t = __shfl_sync(0xffffffffu, myt, j);
                float4 r = reinterpret_cast<const float4*>(rel + (size_t)t * RANK)[lane];
                racc.x += r.x; racc.y += r.y; racc.z += r.z; racc.w += r.w;
            }
        }
    }
    if (mode == 0) {
        reinterpret_cast<float4*>(g_sumrel + (size_t)w * RANK)[lane] = racc;
    } else {
        racc = reinterpret_cast<const float4*>(g_sumrel + (size_t)w * RANK)[lane];
    }
    float nm = norm[w];
    uint2 o;
    o.x = h2u(__floats2half2_rn((acc.x + racc.x) * nm, (acc.y + racc.y) * nm));
    o.y = h2u(__floats2half2_rn((acc.z + racc.z) * nm, (acc.w + racc.w) * nm));
    *reinterpret_cast<uint2*>(g_Af + (size_t)w * 256 + lane * 4) = o;
}

// ---------------- 2-pass fp16 mma.sync GEMM, cp.async double-buffered -----
// D = A@Whi + A@Wlo, K=256 in 8 chunks of 32. A tile shared by both B tiles.
#define NCH   8
#define TROWB 80
#define TILEB (128 * TROWB)
#define GEMM_SMEM (6 * TILEB)      // {A,Bh,Br} x 2 buffers = 61440 B
__global__ void __launch_bounds__(256, 2)
gemm_kernel(int layer, float* __restrict__ out_ext, int write_h) {
    extern __shared__ __align__(16) char smem[];
    float* __restrict__ outf = out_ext ? out_ext : (float*)g_h1;

    const int tid = threadIdx.x;
    const int lane = tid & 31;
    const int wid = tid >> 5;
    const int warp_m = wid & 3;
    const int warp_n = wid >> 2;
    const int block_row = blockIdx.x * 128;

    const u32 sAu  = smem_u32(smem);               // [2][TILEB]
    const u32 sBhU = sAu + 2 * TILEB;              // [2][TILEB]
    const u32 sBrU = sAu + 4 * TILEB;              // [2][TILEB]

    const int l_row0 = tid >> 2;                   // rows 0..63 (i=0), +64 (i=1)
    const int l_c16  = (tid & 3) * 16;

    const int a_q = lane >> 3;
    const int a_row = (lane & 7) + (a_q & 1) * 8;
    const int a_kb = (a_q >> 1) * 16;
    const int b_q = lane >> 3;
    const int b_row = ((b_q >> 1) * 8) + (lane & 7);
    const int b_kb = (b_q & 1) * 16;

    float c[2][8][4];
#pragma unroll
    for (int t = 0; t < 2; t++)
#pragma unroll
        for (int n = 0; n < 8; n++)
#pragma unroll
            for (int r = 0; r < 4; r++) c[t][n][r] = 0.f;

    const char* __restrict__ Wh = (const char*)(g_Wh + ((size_t)layer << 15));
    const char* __restrict__ Wr = (const char*)(g_Wr + ((size_t)layer << 15));

    auto issue = [&](int kc, int buf) {
        const int kbyte = kc * 64;                 // 32 cols * 2B
#pragma unroll
        for (int i = 0; i < 2; i++) {
            int row = l_row0 + i * 64;
            int grow = block_row + row;
            cpa16z(sAu + buf * TILEB + row * TROWB + l_c16,
                   (const char*)g_Af + (size_t)grow * 512 + kbyte + l_c16,
                   (grow < N_ENTS) ? 16 : 0);
            cpa16(sBhU + buf * TILEB + row * TROWB + l_c16,
                  Wh + (size_t)row * 512 + kbyte + l_c16);
            cpa16(sBrU + buf * TILEB + row * TROWB + l_c16,
                  Wr + (size_t)row * 512 + kbyte + l_c16);
        }
    };

    issue(0, 0); cpa_commit();
    issue(1, 1); cpa_commit();

    for (int kc = 0; kc < NCH; kc++) {
        const int buf = kc & 1;
        cpa_wait1();
        __syncthreads();
        const u32 aBase  = sAu  + buf * TILEB;
        const u32 bhBase = sBhU + buf * TILEB;
        const u32 brBase = sBrU + buf * TILEB;
#pragma unroll
        for (int j = 0; j < 2; j++) {
            u32 aa[2][4];
#pragma unroll
            for (int t = 0; t < 2; t++)
                ldmx4(aa[t], aBase + (warp_m * 32 + t * 16 + a_row) * TROWB + j * 32 + a_kb);
#pragma unroll
            for (int p = 0; p < 4; p++) {
                u32 bbh[4], bbr[4];
                u32 boff = (warp_n * 64 + p * 16 + b_row) * TROWB + j * 32 + b_kb;
                ldmx4(bbh, bhBase + boff);
                ldmx4(bbr, brBase + boff);
#pragma unroll
                for (int t = 0; t < 2; t++) {
                    mma16816h(c[t][2 * p],     aa[t], bbh);
                    mma16816h(c[t][2 * p + 1], aa[t], bbh + 2);
                    mma16816h(c[t][2 * p],     aa[t], bbr);
                    mma16816h(c[t][2 * p + 1], aa[t], bbr + 2);
                }
            }
        }
        __syncthreads();
        if (kc + 2 < NCH) issue(kc + 2, buf);
        cpa_commit();
    }

    const int er = lane >> 2;
    const int ec = (lane & 3) * 2;
#pragma unroll
    for (int t = 0; t < 2; t++) {
#pragma unroll
        for (int half = 0; half < 2; half++) {
            int grow = block_row + warp_m * 32 + t * 16 + er + half * 8;
            if (grow >= N_ENTS) continue;
#pragma unroll
            for (int n = 0; n < 8; n++) {
                int col = warp_n * 64 + n * 8 + ec;
                float v0 = c[t][n][half * 2 + 0];
                float v1 = c[t][n][half * 2 + 1];
                v0 = (v0 >= 0.f) ? v0 : v0 * SLOPE;
                v1 = (v1 >= 0.f) ? v1 : v1 * SLOPE;
                *reinterpret_cast<float2*>(outf + (size_t)grow * RANK + col) =
                    make_float2(v0, v1);
                if (write_h)
                    *reinterpret_cast<u32*>(g_Af + (size_t)grow * 256 + 128 + col) =
                        h2u(__floats2half2_rn(v0, v1));
            }
        }
    }
}

// ---------------- deg-0 fixup ----------------
__global__ void fixup_kernel(const float* __restrict__ h_ext,
                             const float* __restrict__ Wa,
                             float* __restrict__ out_ext, int write_h,
                             int zero_after) {
    const float* __restrict__ h = h_ext ? h_ext : (const float*)g_h1;
    float* __restrict__ Out = out_ext ? out_ext : (float*)g_h1;
    int wg = (blockIdx.x * blockDim.x + threadIdx.x) >> 5;
    int lane = threadIdx.x & 31;
    int nwarp = (gridDim.x * blockDim.x) >> 5;
    int cnt = g_deg0_count;
    for (int idx = wg; idx < cnt; idx += nwarp) {
        int v = g_deg0_list[idx];
        const float* hr = h + (size_t)v * RANK;
        float4 acc = make_float4(0.f, 0.f, 0.f, 0.f);
        for (int k = 0; k < RANK; k++) {
            float a = hr[k];
            float4 wv = reinterpret_cast<const float4*>(Wa + (size_t)k * RANK)[lane];
            acc.x += a * wv.x; acc.y += a * wv.y;
            acc.z += a * wv.z; acc.w += a * wv.w;
        }
        float f0 = (acc.x >= 0.f) ? acc.x : acc.x * SLOPE;
        float f1 = (acc.y >= 0.f) ? acc.y : acc.y * SLOPE;
        float f2 = (acc.z >= 0.f) ? acc.z : acc.z * SLOPE;
        float f3 = (acc.w >= 0.f) ? acc.w : acc.w * SLOPE;
        reinterpret_cast<float4*>(Out + (size_t)v * RANK)[lane] =
            make_float4(f0, f1, f2, f3);
        if (write_h) {
            uint2 o;
            o.x = h2u(__floats2half2_rn(f0, f1));
            o.y = h2u(__floats2half2_rn(f2, f3));
            *reinterpret_cast<uint2*>(g_Af + (size_t)v * 256 + 128 + lane * 4) = o;
        }
    }
    if (zero_after) {                 // single-block launch only
        __syncthreads();
        if (threadIdx.x == 0) g_deg0_count = 0;
    }
}

// ---------------- launch ----------------
extern "C" void kernel_launch(void* const* d_in, const int* in_sizes, int n_in,
                              void* d_out, int out_size) {
    const float* ent  = (const float*)d_in[0];
    const float* rel  = (const float*)d_in[1];
    const float* norm = (const float*)d_in[2];
    const float* Wn   = (const float*)d_in[3];
    const float* Wl   = (const float*)d_in[4];
    const float* Wa   = (const float*)d_in[5];
    const int*   src  = (const int*)d_in[6];
    const int*   dst  = (const int*)d_in[7];
    const int*   et   = (const int*)d_in[8];
    float* out = (float*)d_out;

    const int EB  = (N_EDGES + 255) / 256;
    const int AGB = (N_ENTS * 32 + 255) / 256;
    const int GB  = (N_ENTS + 127) / 128;
    const int WSTRIDE = RANK * RANK;

    cudaFuncSetAttribute(gemm_kernel,
                         cudaFuncAttributeMaxDynamicSharedMemorySize, GEMM_SMEM);

    hist_kernel<<<EB, 256>>>(dst);                       // 1
    scanA_kernel<<<SNB, 1024>>>();                       // 2
    scanB_kernel<<<1, 64>>>();                           // 3
    scanC_kernel<<<SNB, 1024>>>();                       // 4  <-- ncu capture slot
    fill_kernel<<<EB, 256>>>(src, dst, et);              // 5
    agg_kernel<<<AGB, 256>>>(ent, rel, norm, 0);         // 6
    prep_kernel<<<WTB + ENTB, 256>>>(Wn, Wl, ent);       // 7
    gemm_kernel<<<GB, 256, GEMM_SMEM>>>(0, nullptr, 1);  // 8
    fixup_kernel<<<8, 256>>>(ent, Wa + 0 * WSTRIDE, nullptr, 1, 0);    // 9
    agg_kernel<<<AGB, 256>>>(nullptr, rel, norm, 1);     // 10
    gemm_kernel<<<GB, 256, GEMM_SMEM>>>(1, out, 0);      // 11
    fixup_kernel<<<1, 256>>>(nullptr, Wa + 1 * WSTRIDE, out, 0, 1);    // 12
}